// round 2
// baseline (speedup 1.0000x reference)
#include <cuda_runtime.h>
#include <cstdint>
#include <cstddef>

#define T_STEPS 14
#define BSZ     8192
#define EMBED   256
#define HIDDEN  512
#define VOCAB   193
#define SEQLEN  15

// ---------------- scratch (device globals: allocation-free, ~252 MB) -------
__device__ int   g_is64;
__device__ int   g_tok[T_STEPS * BSZ];
__device__ float g_h0[(size_t)BSZ * HIDDEN];                   // 16 MB
__device__ float g_hs[(size_t)T_STEPS * BSZ * HIDDEN];         // 235 MB

// ---------------- dtype detection for `text` (int64 vs int32) --------------
// If int64 (little-endian), every odd 32-bit word is 0 (tokens < 193).
// If int32, 2048 sampled words all being 0 has probability (1/193)^2048 ~ 0.
__global__ void detect_dtype_kernel(const int* __restrict__ text_words) {
    __shared__ int nz;
    if (threadIdx.x == 0) nz = 0;
    __syncthreads();
    for (int i = threadIdx.x; i < 2048; i += blockDim.x)
        if (text_words[2 * i + 1] != 0) atomicOr(&nz, 1);
    __syncthreads();
    if (threadIdx.x == 0) g_is64 = nz ? 0 : 1;
}

__global__ void convert_tok_kernel(const void* __restrict__ text) {
    int i = blockIdx.x * blockDim.x + threadIdx.x;     // i = b*14 + t
    if (i >= T_STEPS * BSZ) return;
    int b = i / T_STEPS, t = i - b * T_STEPS;
    int src = b * SEQLEN + t;
    int v;
    if (g_is64) v = (int)((const long long*)text)[src];
    else        v = ((const int*)text)[src];
    g_tok[i] = v;
}

// ---------------- generic NT GEMM: C[M,N] = A[M,K] * B[N,K]^T + bias --------
// mode 0: C row-major [M,N]. mode 1: preds remap, row m=t*B+b -> out[b][t][n].
__global__ __launch_bounds__(256) void gemm_nt_kernel(
    const float* __restrict__ A, const float* __restrict__ Bm,
    const float* __restrict__ bias, float* __restrict__ C,
    int M, int N, int K, int mode)
{
    __shared__ float As[16][132];
    __shared__ float Bs[16][132];
    const int tid = threadIdx.x;
    const int m0 = blockIdx.y * 128, n0 = blockIdx.x * 128;
    const int rm = (tid >> 4) * 8, rn = (tid & 15) * 8;

    float acc[8][8];
#pragma unroll
    for (int i = 0; i < 8; i++)
#pragma unroll
        for (int j = 0; j < 8; j++) acc[i][j] = 0.f;

    for (int k0 = 0; k0 < K; k0 += 16) {
#pragma unroll
        for (int l = 0; l < 2; l++) {
            int idx = tid + l * 256;       // 0..511
            int r = idx >> 2, c4 = idx & 3;
            float4 av = make_float4(0.f, 0.f, 0.f, 0.f);
            float4 bv = make_float4(0.f, 0.f, 0.f, 0.f);
            int gm = m0 + r, gn = n0 + r;
            if (gm < M) av = *reinterpret_cast<const float4*>(&A [(size_t)gm * K + k0 + c4 * 4]);
            if (gn < N) bv = *reinterpret_cast<const float4*>(&Bm[(size_t)gn * K + k0 + c4 * 4]);
            As[c4 * 4 + 0][r] = av.x; As[c4 * 4 + 1][r] = av.y;
            As[c4 * 4 + 2][r] = av.z; As[c4 * 4 + 3][r] = av.w;
            Bs[c4 * 4 + 0][r] = bv.x; Bs[c4 * 4 + 1][r] = bv.y;
            Bs[c4 * 4 + 2][r] = bv.z; Bs[c4 * 4 + 3][r] = bv.w;
        }
        __syncthreads();
#pragma unroll
        for (int kk = 0; kk < 16; kk++) {
            float4 a0 = *reinterpret_cast<const float4*>(&As[kk][rm]);
            float4 a1 = *reinterpret_cast<const float4*>(&As[kk][rm + 4]);
            float4 b0 = *reinterpret_cast<const float4*>(&Bs[kk][rn]);
            float4 b1 = *reinterpret_cast<const float4*>(&Bs[kk][rn + 4]);
            float a[8] = {a0.x, a0.y, a0.z, a0.w, a1.x, a1.y, a1.z, a1.w};
            float b[8] = {b0.x, b0.y, b0.z, b0.w, b1.x, b1.y, b1.z, b1.w};
#pragma unroll
            for (int i = 0; i < 8; i++)
#pragma unroll
                for (int j = 0; j < 8; j++) acc[i][j] += a[i] * b[j];
        }
        __syncthreads();
    }

#pragma unroll
    for (int i = 0; i < 8; i++) {
        int gm = m0 + rm + i;
        if (gm >= M) continue;
#pragma unroll
        for (int j = 0; j < 8; j++) {
            int gn = n0 + rn + j;
            if (gn >= N) continue;
            float v = acc[i][j] + (bias ? bias[gn] : 0.f);
            if (mode == 0) {
                C[(size_t)gm * N + gn] = v;
            } else {
                int t = gm >> 13, b = gm & 8191;
                C[((size_t)b * T_STEPS + t) * VOCAB + gn] = v;
            }
        }
    }
}

// ---------------- fully fused GRU step -------------------------------------
// One kernel computes, for a [64 x 64] tile of h_t:
//   phase 1: gi = emb[tok_t] @ W_ih^T   (K = 256, A gathered from emb)
//   phase 2: gh = h_{t-1}  @ W_hh^T     (K = 512)
// with 4 accumulator slabs: 0: r (gi+gh), 1: z (gi+gh), 2: i_n, 3: h_n.
// Epilogue applies sigmoid/tanh gates and writes h_t. No gi/gh HBM traffic.
__global__ __launch_bounds__(256) void gru_step_kernel(
    const float* __restrict__ emb,
    const float* __restrict__ W_ih, const float* __restrict__ W_hh,
    const float* __restrict__ b_ih, const float* __restrict__ b_hh, int t)
{
    __shared__ float As[16][68];
    __shared__ float Bs[3][16][68];

    const float* hp   = (t == 0) ? g_h0 : (g_hs + (size_t)(t - 1) * BSZ * HIDDEN);
    float*       hout = g_hs + (size_t)t * BSZ * HIDDEN;

    const int tid = threadIdx.x;
    const int m0 = blockIdx.y * 64, n0 = blockIdx.x * 64;
    const int rm = (tid >> 4) * 4, rn = (tid & 15) * 4;
    const int r = tid >> 2, c4 = tid & 3;      // loader: row r (0..63), 16B chunk c4

    float acc[4][4][4];
#pragma unroll
    for (int s = 0; s < 4; s++)
#pragma unroll
        for (int i = 0; i < 4; i++)
#pragma unroll
            for (int j = 0; j < 4; j++) acc[s][i][j] = 0.f;

    const int tok = g_tok[(m0 + r) * T_STEPS + t];   // token for row this thread loads

    // -------- phase 1: input projection, K over EMBED (A = emb[tok]) -------
    for (int k0 = 0; k0 < EMBED; k0 += 16) {
        float4 av = *reinterpret_cast<const float4*>(
            &emb[(size_t)tok * EMBED + k0 + c4 * 4]);
        As[c4 * 4 + 0][r] = av.x; As[c4 * 4 + 1][r] = av.y;
        As[c4 * 4 + 2][r] = av.z; As[c4 * 4 + 3][r] = av.w;
#pragma unroll
        for (int s = 0; s < 3; s++) {
            float4 bv = *reinterpret_cast<const float4*>(
                &W_ih[(size_t)(s * HIDDEN + n0 + r) * EMBED + k0 + c4 * 4]);
            Bs[s][c4 * 4 + 0][r] = bv.x; Bs[s][c4 * 4 + 1][r] = bv.y;
            Bs[s][c4 * 4 + 2][r] = bv.z; Bs[s][c4 * 4 + 3][r] = bv.w;
        }
        __syncthreads();
#pragma unroll
        for (int kk = 0; kk < 16; kk++) {
            float4 a4  = *reinterpret_cast<const float4*>(&As[kk][rm]);
            float4 b4r = *reinterpret_cast<const float4*>(&Bs[0][kk][rn]);
            float4 b4z = *reinterpret_cast<const float4*>(&Bs[1][kk][rn]);
            float4 b4n = *reinterpret_cast<const float4*>(&Bs[2][kk][rn]);
            float a[4]  = {a4.x,  a4.y,  a4.z,  a4.w};
            float br[4] = {b4r.x, b4r.y, b4r.z, b4r.w};
            float bz[4] = {b4z.x, b4z.y, b4z.z, b4z.w};
            float bn[4] = {b4n.x, b4n.y, b4n.z, b4n.w};
#pragma unroll
            for (int i = 0; i < 4; i++)
#pragma unroll
                for (int j = 0; j < 4; j++) {
                    acc[0][i][j] += a[i] * br[j];
                    acc[1][i][j] += a[i] * bz[j];
                    acc[2][i][j] += a[i] * bn[j];   // i_n
                }
        }
        __syncthreads();
    }

    // -------- phase 2: recurrent projection, K over HIDDEN (A = h_prev) ----
    for (int k0 = 0; k0 < HIDDEN; k0 += 16) {
        float4 av = *reinterpret_cast<const float4*>(
            &hp[(size_t)(m0 + r) * HIDDEN + k0 + c4 * 4]);
        As[c4 * 4 + 0][r] = av.x; As[c4 * 4 + 1][r] = av.y;
        As[c4 * 4 + 2][r] = av.z; As[c4 * 4 + 3][r] = av.w;
#pragma unroll
        for (int s = 0; s < 3; s++) {
            float4 bv = *reinterpret_cast<const float4*>(
                &W_hh[(size_t)(s * HIDDEN + n0 + r) * HIDDEN + k0 + c4 * 4]);
            Bs[s][c4 * 4 + 0][r] = bv.x; Bs[s][c4 * 4 + 1][r] = bv.y;
            Bs[s][c4 * 4 + 2][r] = bv.z; Bs[s][c4 * 4 + 3][r] = bv.w;
        }
        __syncthreads();
#pragma unroll
        for (int kk = 0; kk < 16; kk++) {
            float4 a4  = *reinterpret_cast<const float4*>(&As[kk][rm]);
            float4 b4r = *reinterpret_cast<const float4*>(&Bs[0][kk][rn]);
            float4 b4z = *reinterpret_cast<const float4*>(&Bs[1][kk][rn]);
            float4 b4n = *reinterpret_cast<const float4*>(&Bs[2][kk][rn]);
            float a[4]  = {a4.x,  a4.y,  a4.z,  a4.w};
            float br[4] = {b4r.x, b4r.y, b4r.z, b4r.w};
            float bz[4] = {b4z.x, b4z.y, b4z.z, b4z.w};
            float bn[4] = {b4n.x, b4n.y, b4n.z, b4n.w};
#pragma unroll
            for (int i = 0; i < 4; i++)
#pragma unroll
                for (int j = 0; j < 4; j++) {
                    acc[0][i][j] += a[i] * br[j];
                    acc[1][i][j] += a[i] * bz[j];
                    acc[3][i][j] += a[i] * bn[j];   // h_n
                }
        }
        __syncthreads();
    }

    // -------- epilogue: GRU gates --------
#pragma unroll
    for (int i = 0; i < 4; i++) {
        int m = m0 + rm + i;
        const float* hrow = hp   + (size_t)m * HIDDEN;
        float*       orow = hout + (size_t)m * HIDDEN;
#pragma unroll
        for (int j = 0; j < 4; j++) {
            int n = n0 + rn + j;
            float gr  = acc[0][i][j] + b_ih[n]              + b_hh[n];
            float gz  = acc[1][i][j] + b_ih[HIDDEN + n]     + b_hh[HIDDEN + n];
            float gin = acc[2][i][j] + b_ih[2 * HIDDEN + n];
            float ghn = acc[3][i][j] + b_hh[2 * HIDDEN + n];
            float rr = 1.f / (1.f + expf(-gr));
            float zz = 1.f / (1.f + expf(-gz));
            float nn = tanhf(gin + rr * ghn);
            orow[n] = (1.f - zz) * nn + zz * hrow[n];
        }
    }
}

// ---------------- launch ----------------
extern "C" void kernel_launch(void* const* d_in, const int* in_sizes, int n_in,
                              void* d_out, int out_size)
{
    const float* img    = (const float*)d_in[0];
    const void*  text   = d_in[1];
    const float* emb    = (const float*)d_in[2];
    const float* W_proj = (const float*)d_in[3];
    const float* b_proj = (const float*)d_in[4];
    const float* W_ih   = (const float*)d_in[5];
    const float* W_hh   = (const float*)d_in[6];
    const float* b_ih   = (const float*)d_in[7];
    const float* b_hh   = (const float*)d_in[8];
    const float* W_out  = (const float*)d_in[9];
    const float* b_out  = (const float*)d_in[10];
    float* out = (float*)d_out;

    float *ph0, *phs;
    cudaGetSymbolAddress((void**)&ph0, g_h0);
    cudaGetSymbolAddress((void**)&phs, g_hs);

    // 1) normalize tokens (handles int64-vs-int32 text)
    detect_dtype_kernel<<<1, 256>>>((const int*)text);
    convert_tok_kernel<<<(T_STEPS * BSZ + 255) / 256, 256>>>(text);

    // 2) h0 = img @ W_proj^T + b_proj     [8192, 512]
    gemm_nt_kernel<<<dim3(HIDDEN / 128, BSZ / 128), 256>>>(
        img, W_proj, b_proj, ph0, BSZ, HIDDEN, 512, 0);

    // 3) 14 fully fused GRU steps (embedding gather + gi GEMM + gh GEMM + gates)
    for (int t = 0; t < T_STEPS; t++)
        gru_step_kernel<<<dim3(HIDDEN / 64, BSZ / 64), 256>>>(
            emb, W_ih, W_hh, b_ih, b_hh, t);

    // 4) preds = hs @ W_out^T + b_out, remapped to [B, T, V]
    gemm_nt_kernel<<<dim3((VOCAB + 127) / 128, (T_STEPS * BSZ) / 128), 256>>>(
        phs, W_out, b_out, out, T_STEPS * BSZ, VOCAB, HIDDEN, 1);
}

// round 5
// speedup vs baseline: 3.0360x; 3.0360x over previous
#include <cuda_runtime.h>
#include <cstdint>
#include <cstddef>

#define T_STEPS 14
#define BSZ     8192
#define EMBED   256
#define HIDDEN  512
#define VOCAB   193
#define SEQLEN  15
#define GW      1536          // 3*HIDDEN

// ---------------- scratch (device globals, ~290 MB total) ------------------
__device__ int   g_is64;
__device__ int   g_tok[T_STEPS * BSZ];
__device__ float g_G  [(size_t)VOCAB * GW];                    // gi lookup table
__device__ float g_gh [(size_t)BSZ * GW];                      // 50 MB (one step)
__device__ float g_h0 [(size_t)BSZ * HIDDEN];                  // 16 MB
__device__ float g_hs [(size_t)T_STEPS * BSZ * HIDDEN];        // 235 MB

// ---------------- token dtype detect + normalize ---------------------------
// If text is int64 (little-endian), every odd 32-bit word is 0 (tokens<193).
// For int32 tokens, 2048 sampled words all-zero has prob (1/193)^2048 ~ 0.
__global__ void detect_dtype_kernel(const int* __restrict__ text_words) {
    __shared__ int nz;
    if (threadIdx.x == 0) nz = 0;
    __syncthreads();
    for (int i = threadIdx.x; i < 2048; i += blockDim.x)
        if (text_words[2 * i + 1] != 0) atomicOr(&nz, 1);
    __syncthreads();
    if (threadIdx.x == 0) g_is64 = nz ? 0 : 1;
}

__global__ void convert_tok_kernel(const void* __restrict__ text) {
    int i = blockIdx.x * blockDim.x + threadIdx.x;     // i = b*14 + t
    if (i >= T_STEPS * BSZ) return;
    int b = i / T_STEPS, t = i - b * T_STEPS;
    int src = b * SEQLEN + t;
    int v;
    if (g_is64) v = (int)((const long long*)text)[src];
    else        v = ((const int*)text)[src];
    g_tok[i] = v;
}

// ---------------- G table: G[v][n] = emb[v] . W_ih[n] + b_ih[n] (fp32) -----
// Only 193*1536 outputs; fp32 dot keeps the input-path exact.
__global__ void build_G_kernel(const float* __restrict__ emb,
                               const float* __restrict__ W_ih,
                               const float* __restrict__ b_ih) {
    int idx = blockIdx.x * blockDim.x + threadIdx.x;
    if (idx >= VOCAB * GW) return;
    int v = idx / GW, n = idx - v * GW;
    const float* er = emb  + (size_t)v * EMBED;
    const float* wr = W_ih + (size_t)n * EMBED;
    float s = b_ih[n];
#pragma unroll 8
    for (int k = 0; k < EMBED; k++) s += er[k] * wr[k];
    g_G[idx] = s;
}

// ---------------- generic tf32 tensor-core NT GEMM -------------------------
// C[M,N] = A[M,K] @ B[N,K]^T (+bias). K % 32 == 0, M % 128 == 0.
// mode 0: C[m*ldc+n].  mode 1: preds remap m=t*BSZ+b -> out[(b*14+t)*VOCAB+n].
__device__ __forceinline__ uint32_t f2tf32(float f) {
    uint32_t r;
    asm("cvt.rna.tf32.f32 %0, %1;" : "=r"(r) : "f"(f));
    return r;
}
__device__ __forceinline__ void mma_tf32(float c[4], const uint32_t a[4],
                                         const uint32_t b[2]) {
    asm volatile(
        "mma.sync.aligned.m16n8k8.row.col.f32.tf32.tf32.f32 "
        "{%0,%1,%2,%3}, {%4,%5,%6,%7}, {%8,%9}, {%0,%1,%2,%3};"
        : "+f"(c[0]), "+f"(c[1]), "+f"(c[2]), "+f"(c[3])
        : "r"(a[0]), "r"(a[1]), "r"(a[2]), "r"(a[3]), "r"(b[0]), "r"(b[1]));
}

#define LDA_S 36   // smem row pitch (uint32): stride 36 -> conflict-free frag loads

__global__ __launch_bounds__(256, 2) void gemm_tf32_kernel(
    const float* __restrict__ A, const float* __restrict__ Bm,
    const float* __restrict__ bias, float* __restrict__ C,
    int M, int N, int K, int ldc, int mode)
{
    __shared__ uint32_t As[128 * LDA_S];   // 18.4 KB
    __shared__ uint32_t Bs[128 * LDA_S];   // 18.4 KB

    const int tid  = threadIdx.x;
    const int lane = tid & 31, warp = tid >> 5;
    const int g = lane >> 2, t4 = lane & 3;
    const int m0 = blockIdx.y * 128, n0 = blockIdx.x * 128;
    const int wm0 = (warp >> 2) * 64, wn0 = (warp & 3) * 32;

    float acc[4][4][4];
#pragma unroll
    for (int mf = 0; mf < 4; mf++)
#pragma unroll
        for (int nf = 0; nf < 4; nf++)
#pragma unroll
            for (int e = 0; e < 4; e++) acc[mf][nf][e] = 0.f;

    for (int k0 = 0; k0 < K; k0 += 32) {
        // ---- load A,B tiles (128x32 each), convert to tf32 ----
#pragma unroll
        for (int it = 0; it < 4; it++) {
            int idx = tid + it * 256;          // 0..1023
            int row = idx >> 3, c4 = idx & 7;  // c4: which float4 of 8
            float4 av = *reinterpret_cast<const float4*>(
                &A[(size_t)(m0 + row) * K + k0 + c4 * 4]);
            uint32_t* d = &As[row * LDA_S + c4 * 4];
            d[0] = f2tf32(av.x); d[1] = f2tf32(av.y);
            d[2] = f2tf32(av.z); d[3] = f2tf32(av.w);

            int gn = n0 + row;
            float4 bv = make_float4(0.f, 0.f, 0.f, 0.f);
            if (gn < N)
                bv = *reinterpret_cast<const float4*>(
                    &Bm[(size_t)gn * K + k0 + c4 * 4]);
            uint32_t* e = &Bs[row * LDA_S + c4 * 4];
            e[0] = f2tf32(bv.x); e[1] = f2tf32(bv.y);
            e[2] = f2tf32(bv.z); e[3] = f2tf32(bv.w);
        }
        __syncthreads();

        // ---- 4 k-steps of 8 ----
#pragma unroll
        for (int ks = 0; ks < 4; ks++) {
            uint32_t afr[4][4];
#pragma unroll
            for (int mf = 0; mf < 4; mf++) {
                const uint32_t* base = &As[(wm0 + mf * 16 + g) * LDA_S + ks * 8 + t4];
                afr[mf][0] = base[0];
                afr[mf][1] = base[8 * LDA_S];
                afr[mf][2] = base[4];
                afr[mf][3] = base[8 * LDA_S + 4];
            }
            uint32_t bfr[4][2];
#pragma unroll
            for (int nf = 0; nf < 4; nf++) {
                const uint32_t* base = &Bs[(wn0 + nf * 8 + g) * LDA_S + ks * 8 + t4];
                bfr[nf][0] = base[0];
                bfr[nf][1] = base[4];
            }
#pragma unroll
            for (int mf = 0; mf < 4; mf++)
#pragma unroll
                for (int nf = 0; nf < 4; nf++)
                    mma_tf32(acc[mf][nf], afr[mf], bfr[nf]);
        }
        __syncthreads();
    }

    // ---- epilogue ----
#pragma unroll
    for (int mf = 0; mf < 4; mf++) {
#pragma unroll
        for (int nf = 0; nf < 4; nf++) {
            int nbase = n0 + wn0 + nf * 8 + t4 * 2;
            float bias0 = 0.f, bias1 = 0.f;
            if (bias) {
                if (nbase < N)     bias0 = bias[nbase];
                if (nbase + 1 < N) bias1 = bias[nbase + 1];
            }
#pragma unroll
            for (int e = 0; e < 4; e++) {
                int m = m0 + wm0 + mf * 16 + g + ((e >= 2) ? 8 : 0);
                int n = nbase + (e & 1);
                if (n >= N) continue;
                float v = acc[mf][nf][e] + ((e & 1) ? bias1 : bias0);
                if (mode == 0) {
                    C[(size_t)m * ldc + n] = v;
                } else {
                    int t = m >> 13, b = m & (BSZ - 1);
                    C[((size_t)b * T_STEPS + t) * VOCAB + n] = v;
                }
            }
        }
    }
}

// ---------------- gate kernel: h_t = GRU(G[tok], gh, h_prev) ---------------
__global__ __launch_bounds__(256) void gate_kernel(int t)
{
    int idx = blockIdx.x * blockDim.x + threadIdx.x;   // one per 4 elems
    if (idx >= BSZ * (HIDDEN / 4)) return;
    int m = idx >> 7;            // HIDDEN/4 = 128
    int n = (idx & 127) * 4;

    const float* hp = (t == 0) ? g_h0 : (g_hs + (size_t)(t - 1) * BSZ * HIDDEN);
    float* hout = g_hs + (size_t)t * BSZ * HIDDEN;
    int tok = g_tok[m * T_STEPS + t];

    const float* Gr = g_G  + (size_t)tok * GW;
    const float* gh = g_gh + (size_t)m * GW;

    float4 gir = *reinterpret_cast<const float4*>(&Gr[n]);
    float4 giz = *reinterpret_cast<const float4*>(&Gr[HIDDEN + n]);
    float4 gin = *reinterpret_cast<const float4*>(&Gr[2 * HIDDEN + n]);
    float4 ghr = *reinterpret_cast<const float4*>(&gh[n]);
    float4 ghz = *reinterpret_cast<const float4*>(&gh[HIDDEN + n]);
    float4 ghn = *reinterpret_cast<const float4*>(&gh[2 * HIDDEN + n]);
    float4 hv  = *reinterpret_cast<const float4*>(&hp[(size_t)m * HIDDEN + n]);

    float4 o;
    {
        float r = 1.f / (1.f + expf(-(gir.x + ghr.x)));
        float z = 1.f / (1.f + expf(-(giz.x + ghz.x)));
        float nn = tanhf(gin.x + r * ghn.x);
        o.x = (1.f - z) * nn + z * hv.x;
    }
    {
        float r = 1.f / (1.f + expf(-(gir.y + ghr.y)));
        float z = 1.f / (1.f + expf(-(giz.y + ghz.y)));
        float nn = tanhf(gin.y + r * ghn.y);
        o.y = (1.f - z) * nn + z * hv.y;
    }
    {
        float r = 1.f / (1.f + expf(-(gir.z + ghr.z)));
        float z = 1.f / (1.f + expf(-(giz.z + ghz.z)));
        float nn = tanhf(gin.z + r * ghn.z);
        o.z = (1.f - z) * nn + z * hv.z;
    }
    {
        float r = 1.f / (1.f + expf(-(gir.w + ghr.w)));
        float z = 1.f / (1.f + expf(-(giz.w + ghz.w)));
        float nn = tanhf(gin.w + r * ghn.w);
        o.w = (1.f - z) * nn + z * hv.w;
    }
    *reinterpret_cast<float4*>(&hout[(size_t)m * HIDDEN + n]) = o;
}

// ---------------- launch ----------------
extern "C" void kernel_launch(void* const* d_in, const int* in_sizes, int n_in,
                              void* d_out, int out_size)
{
    const float* img    = (const float*)d_in[0];
    const void*  text   = d_in[1];
    const float* emb    = (const float*)d_in[2];
    const float* W_proj = (const float*)d_in[3];
    const float* b_proj = (const float*)d_in[4];
    const float* W_ih   = (const float*)d_in[5];
    const float* W_hh   = (const float*)d_in[6];
    const float* b_ih   = (const float*)d_in[7];
    const float* b_hh   = (const float*)d_in[8];
    const float* W_out  = (const float*)d_in[9];
    const float* b_out  = (const float*)d_in[10];
    float* out = (float*)d_out;

    float *ph0, *phs, *pgh;
    cudaGetSymbolAddress((void**)&ph0, g_h0);
    cudaGetSymbolAddress((void**)&phs, g_hs);
    cudaGetSymbolAddress((void**)&pgh, g_gh);

    // 1) tokens
    detect_dtype_kernel<<<1, 256>>>((const int*)text);
    convert_tok_kernel<<<(T_STEPS * BSZ + 255) / 256, 256>>>(text);

    // 2) G lookup table (replaces the entire input-projection GEMM)
    build_G_kernel<<<(VOCAB * GW + 255) / 256, 256>>>(emb, W_ih, b_ih);

    // 3) h0 = img @ W_proj^T + b_proj   [8192, 512]
    gemm_tf32_kernel<<<dim3(HIDDEN / 128, BSZ / 128), 256>>>(
        img, W_proj, b_proj, ph0, BSZ, HIDDEN, 512, HIDDEN, 0);

    // 4) 14 GRU steps: gh GEMM (tensor) + fused gate elementwise
    for (int t = 0; t < T_STEPS; t++) {
        const float* hp = (t == 0) ? ph0 : (phs + (size_t)(t - 1) * BSZ * HIDDEN);
        gemm_tf32_kernel<<<dim3(GW / 128, BSZ / 128), 256>>>(
            hp, W_hh, b_hh, pgh, BSZ, GW, HIDDEN, GW, 0);
        gate_kernel<<<(BSZ * (HIDDEN / 4) + 255) / 256, 256>>>(t);
    }

    // 5) preds = hs @ W_out^T + b_out, remapped to [B, T, V]
    gemm_tf32_kernel<<<dim3(2, (T_STEPS * BSZ) / 128), 256>>>(
        phs, W_out, b_out, out, T_STEPS * BSZ, VOCAB, HIDDEN, VOCAB, 1);
}